// round 10
// baseline (speedup 1.0000x reference)
#include <cuda_runtime.h>
#include <math.h>

#define N_NODES 50000
#define NUM_E   400000
#define ETOT    (NUM_E + N_NODES)   // 450000, self-loops appended
#define IN_C    128
#define HID     32
#define HEADS   8
#define F1      (HEADS * HID)       // 256
#define OUT_C   64
#define K_CL    16
#define NEG_SLOPE 0.2f
#define EPS_F   1e-16f

// ---------------- scratch (device globals; no runtime allocation) -----------
__device__ float g_h1[(size_t)N_NODES * F1];     // x@W1
__device__ float g_out1[(size_t)N_NODES * F1];   // layer1 output (incl. b1)
__device__ float g_h2[(size_t)N_NODES * OUT_C];  // ELU(out1)@W2
__device__ float g_asrc1[N_NODES * HEADS];
__device__ float g_adst1[N_NODES * HEADS];
__device__ float g_asrc2[N_NODES];
__device__ float g_adst2[N_NODES];
// CSR by destination
__device__ int g_deg[N_NODES];
__device__ int g_start[N_NODES + 1];
__device__ int g_cursor[N_NODES];
__device__ int g_csr_src[ETOT];
// pre-split weights (packed bf16x2 along k-pairs): [K/2][N]
__device__ unsigned g_w1hi[(IN_C / 2) * F1];
__device__ unsigned g_w1lo[(IN_C / 2) * F1];
__device__ unsigned g_w2hi[(F1 / 2) * OUT_C];
__device__ unsigned g_w2lo[(F1 / 2) * OUT_C];

// ---------------- helpers ----------------------------------------------------
__device__ __forceinline__ float lrelu(float x) { return x > 0.f ? x : NEG_SLOPE * x; }
__device__ __forceinline__ float elu1(float x)  { return x > 0.f ? x : expm1f(x); }

__device__ __forceinline__ unsigned pack_bf16(float f_even, float f_odd) {
    unsigned r;
    asm("cvt.rn.satfinite.bf16x2.f32 %0, %1, %2;" : "=r"(r) : "f"(f_odd), "f"(f_even));
    return r;
}
__device__ __forceinline__ void bf16_split(float f0, float f1, unsigned& hi, unsigned& lo) {
    hi = pack_bf16(f0, f1);
    float b0 = __uint_as_float(hi << 16);
    float b1 = __uint_as_float(hi & 0xffff0000u);
    lo = pack_bf16(f0 - b0, f1 - b1);
}

#define MMA_BF16(d, a, b0_, b1_) \
    asm("mma.sync.aligned.m16n8k16.row.col.f32.bf16.bf16.f32 " \
        "{%0,%1,%2,%3}, {%4,%5,%6,%7}, {%8,%9}, {%0,%1,%2,%3};" \
        : "+f"(d[0]), "+f"(d[1]), "+f"(d[2]), "+f"(d[3]) \
        : "r"(a[0]), "r"(a[1]), "r"(a[2]), "r"(a[3]), "r"(b0_), "r"(b1_))

// ---------------- prep: zero degree hist + split both weight matrices --------
__global__ void prep_kernel(const float* __restrict__ W1, const float* __restrict__ W2) {
    int b = blockIdx.x, tid = threadIdx.x;
    if (b < 196) {
        int i = b * 256 + tid;
        if (i < N_NODES) g_deg[i] = 0;
    } else if (b < 196 + 64) {               // W1: (IN_C/2)*F1 = 16384 = 64*256
        int i = (b - 196) * 256 + tid;
        int kp = i >> 8, n = i & 255;
        unsigned h, l;
        bf16_split(W1[(size_t)(2 * kp) * F1 + n], W1[(size_t)(2 * kp + 1) * F1 + n], h, l);
        g_w1hi[i] = h; g_w1lo[i] = l;
    } else {                                  // W2: (F1/2)*OUT_C = 8192 = 32*256
        int i = (b - 260) * 256 + tid;
        int kp = i >> 6, n = i & 63;
        unsigned h, l;
        bf16_split(W2[(size_t)(2 * kp) * OUT_C + n], W2[(size_t)(2 * kp + 1) * OUT_C + n], h, l);
        g_w2hi[i] = h; g_w2lo[i] = l;
    }
}

// ---------------- edge histogram ---------------------------------------------
__global__ void hist_kernel(const int* __restrict__ ei) {
    int e = blockIdx.x * blockDim.x + threadIdx.x;
    if (e >= ETOT) return;
    int d = (e < NUM_E) ? ei[NUM_E + e] : e - NUM_E;
    atomicAdd(&g_deg[d], 1);
}

// ---------------- CSR: single-block scan + scatter ---------------------------
__global__ void scan_all() {
    __shared__ int sm[256];
    const int CH = 196;                       // 256*196 = 50176 >= N_NODES
    int tid = threadIdx.x;
    int base = tid * CH;
    int sum = 0;
    for (int i = 0; i < CH; i++) {
        int idx = base + i;
        if (idx < N_NODES) sum += g_deg[idx];
    }
    sm[tid] = sum;
    __syncthreads();
    #pragma unroll
    for (int off = 1; off < 256; off <<= 1) {
        int t = (tid >= off) ? sm[tid - off] : 0;
        __syncthreads();
        sm[tid] += t;
        __syncthreads();
    }
    int run = sm[tid] - sum;                  // exclusive prefix of this chunk
    for (int i = 0; i < CH; i++) {
        int idx = base + i;
        if (idx < N_NODES) {
            g_start[idx] = run;
            g_cursor[idx] = run;
            run += g_deg[idx];
        }
    }
    if (tid == 0) g_start[N_NODES] = ETOT;
}
__global__ void scatter_kernel(const int* __restrict__ ei) {
    int e = blockIdx.x * blockDim.x + threadIdx.x;
    if (e >= ETOT) return;
    int s, d;
    if (e < NUM_E) { s = ei[e]; d = ei[NUM_E + e]; } else { s = d = e - NUM_E; }
    int pos = atomicAdd(&g_cursor[d], 1);
    g_csr_src[pos] = s;
}

// ---------------- bf16 3-product tensor-core GEMM ----------------------------
#define AS_STRIDE 20
template<int BN, bool ELU_A>
__global__ __launch_bounds__(256, 2) void gemm_bf16x3(
    const float* __restrict__ A,
    const unsigned* __restrict__ Bhi, const unsigned* __restrict__ Blo,
    float* __restrict__ C, int M, int Nc, int Kc)
{
    constexpr int NATOM = BN / 16;
    constexpr int BS_STRIDE = BN + 8;
    __shared__ unsigned sAhi[128 * AS_STRIDE];
    __shared__ unsigned sAlo[128 * AS_STRIDE];
    __shared__ unsigned sBhi[16 * BS_STRIDE];
    __shared__ unsigned sBlo[16 * BS_STRIDE];

    const int tid = threadIdx.x;
    const int warp = tid >> 5, lane = tid & 31;
    const int g = lane >> 2, tig = lane & 3;
    const int rowA = blockIdx.y * 128, colB = blockIdx.x * BN;
    const int wm = (warp >> 1) * 32, wn = (warp & 1) * (BN / 2);

    float d[2][NATOM][4];
    #pragma unroll
    for (int i = 0; i < 2; i++)
        #pragma unroll
        for (int j = 0; j < NATOM; j++)
            #pragma unroll
            for (int q = 0; q < 4; q++) d[i][j][q] = 0.f;

    const int arow = tid >> 1;
    const int ak0  = (tid & 1) * 16;
    const bool arow_ok = (rowA + arow) < M;
    const float* Aptr = A + (size_t)(rowA + arow) * Kc + ak0;

    const int bkp = tid >> 4;
    const int bn0 = (tid & 15) * (BN / 16);

    const int KT = Kc / 32;
    for (int kt = 0; kt < KT; kt++) {
        {
            float4 f[4];
            #pragma unroll
            for (int q = 0; q < 4; q++)
                f[q] = arow_ok ? *(const float4*)(Aptr + kt * 32 + q * 4)
                               : make_float4(0.f, 0.f, 0.f, 0.f);
            if (ELU_A) {
                #pragma unroll
                for (int q = 0; q < 4; q++) {
                    f[q].x = elu1(f[q].x); f[q].y = elu1(f[q].y);
                    f[q].z = elu1(f[q].z); f[q].w = elu1(f[q].w);
                }
            }
            unsigned* hp = sAhi + arow * AS_STRIDE + (ak0 >> 1);
            unsigned* lp = sAlo + arow * AS_STRIDE + (ak0 >> 1);
            #pragma unroll
            for (int q = 0; q < 4; q++) {
                unsigned h0, l0, h1, l1;
                bf16_split(f[q].x, f[q].y, h0, l0);
                bf16_split(f[q].z, f[q].w, h1, l1);
                hp[q * 2] = h0; hp[q * 2 + 1] = h1;
                lp[q * 2] = l0; lp[q * 2 + 1] = l1;
            }
        }
        {
            const unsigned* gh = Bhi + (size_t)(kt * 16 + bkp) * Nc + colB + bn0;
            const unsigned* gl = Blo + (size_t)(kt * 16 + bkp) * Nc + colB + bn0;
            unsigned* sh = sBhi + bkp * BS_STRIDE + bn0;
            unsigned* sl = sBlo + bkp * BS_STRIDE + bn0;
            #pragma unroll
            for (int q = 0; q < BN / 64; q++) {
                ((int4*)sh)[q] = ((const int4*)gh)[q];
                ((int4*)sl)[q] = ((const int4*)gl)[q];
            }
        }
        __syncthreads();

        #pragma unroll
        for (int s = 0; s < 2; s++) {
            const int kp = s * 8 + tig;
            unsigned ahi[2][4], alo[2][4];
            #pragma unroll
            for (int am = 0; am < 2; am++) {
                int m0 = wm + am * 16 + g;
                ahi[am][0] = sAhi[m0 * AS_STRIDE + kp];
                ahi[am][1] = sAhi[(m0 + 8) * AS_STRIDE + kp];
                ahi[am][2] = sAhi[m0 * AS_STRIDE + kp + 4];
                ahi[am][3] = sAhi[(m0 + 8) * AS_STRIDE + kp + 4];
                alo[am][0] = sAlo[m0 * AS_STRIDE + kp];
                alo[am][1] = sAlo[(m0 + 8) * AS_STRIDE + kp];
                alo[am][2] = sAlo[m0 * AS_STRIDE + kp + 4];
                alo[am][3] = sAlo[(m0 + 8) * AS_STRIDE + kp + 4];
            }
            #pragma unroll
            for (int an = 0; an < NATOM; an++) {
                int n = wn + an * 8 + g;
                unsigned bh0 = sBhi[kp * BS_STRIDE + n];
                unsigned bh1 = sBhi[(kp + 4) * BS_STRIDE + n];
                unsigned bl0 = sBlo[kp * BS_STRIDE + n];
                unsigned bl1 = sBlo[(kp + 4) * BS_STRIDE + n];
                #pragma unroll
                for (int am = 0; am < 2; am++) {
                    MMA_BF16(d[am][an], ahi[am], bh0, bh1);
                    MMA_BF16(d[am][an], alo[am], bh0, bh1);
                    MMA_BF16(d[am][an], ahi[am], bl0, bl1);
                }
            }
        }
        __syncthreads();
    }

    #pragma unroll
    for (int am = 0; am < 2; am++) {
        int r0 = rowA + wm + am * 16 + g;
        #pragma unroll
        for (int an = 0; an < NATOM; an++) {
            int c = colB + wn + an * 8 + 2 * tig;
            if (r0 < M)
                *(float2*)&C[(size_t)r0 * Nc + c] = make_float2(d[am][an][0], d[am][an][1]);
            if (r0 + 8 < M)
                *(float2*)&C[(size_t)(r0 + 8) * Nc + c] = make_float2(d[am][an][2], d[am][an][3]);
        }
    }
}

// ---------------- attention dot products -------------------------------------
__global__ void att1_kernel(const float* __restrict__ att_src, const float* __restrict__ att_dst) {
    int idx = blockIdx.x * blockDim.x + threadIdx.x;
    if (idx >= N_NODES * HEADS) return;
    int n = idx >> 3, h = idx & 7;
    const float4* hp = (const float4*)(g_h1 + (size_t)n * F1 + h * HID);
    const float4* as = (const float4*)(att_src + h * HID);
    const float4* ad = (const float4*)(att_dst + h * HID);
    float s = 0.f, d = 0.f;
    #pragma unroll
    for (int i = 0; i < 8; i++) {
        float4 hv = hp[i], a = as[i], b = ad[i];
        s += hv.x * a.x + hv.y * a.y + hv.z * a.z + hv.w * a.w;
        d += hv.x * b.x + hv.y * b.y + hv.z * b.z + hv.w * b.w;
    }
    g_asrc1[idx] = s;
    g_adst1[idx] = d;
}

__global__ void att2_kernel(const float* __restrict__ att_src, const float* __restrict__ att_dst) {
    int n = blockIdx.x * blockDim.x + threadIdx.x;
    if (n >= N_NODES) return;
    const float4* hp = (const float4*)(g_h2 + (size_t)n * OUT_C);
    const float4* as = (const float4*)att_src;
    const float4* ad = (const float4*)att_dst;
    float s = 0.f, d = 0.f;
    #pragma unroll
    for (int i = 0; i < 16; i++) {
        float4 hv = hp[i], a = as[i], b = ad[i];
        s += hv.x * a.x + hv.y * a.y + hv.z * a.z + hv.w * a.w;
        d += hv.x * b.x + hv.y * b.y + hv.z * b.z + hv.w * b.w;
    }
    g_asrc2[n] = s;
    g_adst2[n] = d;
}

// ---------------- GAT layer 1: single-pass, lane-batched (warp/node) ---------
// w-precompute: lane l covers edge (l>>3), head (l&7) of each 4-edge batch.
// aggregation: lane l covers columns [l*8, l*8+8) -> head l>>2.
__global__ __launch_bounds__(256) void gat1_csr(const float* __restrict__ b1) {
    int warp = threadIdx.x >> 5, lane = threadIdx.x & 31;
    int n = blockIdx.x * 8 + warp;
    if (n >= N_NODES) return;
    int beg = g_start[n], end = g_start[n + 1];
    int head = lane >> 2;
    int myh = lane & 7, myj = lane >> 3;
    float adst_my = g_adst1[n * 8 + myh];

    float4 a0 = make_float4(0.f, 0.f, 0.f, 0.f);
    float4 a1 = make_float4(0.f, 0.f, 0.f, 0.f);
    float den = 0.f;   // identical across the 4 lanes of each head

    int e = beg;
    int nfull = beg + ((end - beg) & ~3);
    for (; e < nfull; e += 4) {
        int s_my = g_csr_src[e + myj];
        float w_my = __expf(lrelu(g_asrc1[s_my * 8 + myh] + adst_my));
        int   s[4];
        float w[4];
        #pragma unroll
        for (int j = 0; j < 4; j++) {
            s[j] = __shfl_sync(0xffffffffu, s_my, j * 8);
            w[j] = __shfl_sync(0xffffffffu, w_my, j * 8 + head);
        }
        float4 v0[4], v1[4];
        #pragma unroll
        for (int j = 0; j < 4; j++) {
            const float4* hp = (const float4*)(g_h1 + (size_t)s[j] * F1) + lane * 2;
            v0[j] = hp[0]; v1[j] = hp[1];
        }
        #pragma unroll
        for (int j = 0; j < 4; j++) {
            den += w[j];
            a0.x += w[j] * v0[j].x; a0.y += w[j] * v0[j].y;
            a0.z += w[j] * v0[j].z; a0.w += w[j] * v0[j].w;
            a1.x += w[j] * v1[j].x; a1.y += w[j] * v1[j].y;
            a1.z += w[j] * v1[j].z; a1.w += w[j] * v1[j].w;
        }
    }
    int rem = end - e;
    if (rem > 0) {
        int s_my = g_csr_src[(myj < rem) ? (e + myj) : e];
        float w_my = __expf(lrelu(g_asrc1[s_my * 8 + myh] + adst_my));
        for (int j = 0; j < rem; j++) {
            int   sj = __shfl_sync(0xffffffffu, s_my, j * 8);
            float wj = __shfl_sync(0xffffffffu, w_my, j * 8 + head);
            const float4* hp = (const float4*)(g_h1 + (size_t)sj * F1) + lane * 2;
            float4 v0 = hp[0], v1 = hp[1];
            den += wj;
            a0.x += wj * v0.x; a0.y += wj * v0.y; a0.z += wj * v0.z; a0.w += wj * v0.w;
            a1.x += wj * v1.x; a1.y += wj * v1.y; a1.z += wj * v1.z; a1.w += wj * v1.w;
        }
    }
    float inv = 1.f / (den + EPS_F);
    float4 bb0 = ((const float4*)b1)[lane * 2];
    float4 bb1 = ((const float4*)b1)[lane * 2 + 1];
    float4 o0 = make_float4(bb0.x + a0.x * inv, bb0.y + a0.y * inv,
                            bb0.z + a0.z * inv, bb0.w + a0.w * inv);
    float4 o1 = make_float4(bb1.x + a1.x * inv, bb1.y + a1.y * inv,
                            bb1.z + a1.z * inv, bb1.w + a1.w * inv);
    float4* op = (float4*)(g_out1 + (size_t)n * F1) + lane * 2;
    op[0] = o0; op[1] = o1;
}

// ---------------- GAT layer 2: single-pass, lane-batched (warp/node) ---------
__global__ __launch_bounds__(256) void gat2_csr(float* __restrict__ emb, const float* __restrict__ b2) {
    int warp = threadIdx.x >> 5, lane = threadIdx.x & 31;
    int n = blockIdx.x * 8 + warp;
    if (n >= N_NODES) return;
    int beg = g_start[n], end = g_start[n + 1];
    float adst = g_adst2[n];

    float2 acc = make_float2(0.f, 0.f);
    float denl = 0.f;
    for (int eb = beg; eb < end; eb += 32) {
        int e = eb + lane;
        int s_my = 0;
        float w_my = 0.f;
        if (e < end) {
            s_my = g_csr_src[e];
            w_my = __expf(lrelu(g_asrc2[s_my] + adst));
            denl += w_my;
        }
        int cnt = min(32, end - eb);
        int j = 0;
        for (; j + 4 <= cnt; j += 4) {
            int s[4]; float w[4];
            #pragma unroll
            for (int q = 0; q < 4; q++) {
                s[q] = __shfl_sync(0xffffffffu, s_my, j + q);
                w[q] = __shfl_sync(0xffffffffu, w_my, j + q);
            }
            float2 v[4];
            #pragma unroll
            for (int q = 0; q < 4; q++)
                v[q] = *(const float2*)(g_h2 + (size_t)s[q] * OUT_C + lane * 2);
            #pragma unroll
            for (int q = 0; q < 4; q++) {
                acc.x += w[q] * v[q].x;
                acc.y += w[q] * v[q].y;
            }
        }
        for (; j < cnt; j++) {
            int   sj = __shfl_sync(0xffffffffu, s_my, j);
            float wj = __shfl_sync(0xffffffffu, w_my, j);
            float2 v = *(const float2*)(g_h2 + (size_t)sj * OUT_C + lane * 2);
            acc.x += wj * v.x;
            acc.y += wj * v.y;
        }
    }
    float den = denl;
    #pragma unroll
    for (int m = 16; m >= 1; m >>= 1) den += __shfl_xor_sync(0xffffffffu, den, m);
    float inv = 1.f / (den + EPS_F);
    float2 bb = *(const float2*)(b2 + lane * 2);
    *(float2*)(emb + (size_t)n * OUT_C + lane * 2) =
        make_float2(bb.x + acc.x * inv, bb.y + acc.y * inv);
}

// ---------------- fused MLP head + softmax (32 nodes/block) ------------------
__global__ __launch_bounds__(256) void mlp_kernel(
    const float* __restrict__ emb,
    const float* __restrict__ Wm1, const float* __restrict__ bm1,
    const float* __restrict__ Wm2, const float* __restrict__ bm2,
    float* __restrict__ s_out)
{
    __shared__ float sW1[OUT_C * 128];   // 32 KB
    __shared__ float sW2[128 * K_CL];    // 8 KB
    __shared__ float sb1[128];
    __shared__ float sb2[K_CL];
    __shared__ float sHid[8][128];
    __shared__ float sEmb[8][OUT_C];
    int tid = threadIdx.x;
    for (int i = tid; i < OUT_C * 128; i += 256) sW1[i] = Wm1[i];
    for (int i = tid; i < 128 * K_CL; i += 256) sW2[i] = Wm2[i];
    if (tid < 128) sb1[tid] = bm1[tid];
    if (tid < K_CL) sb2[tid] = bm2[tid];
    __syncthreads();
    int warp = tid >> 5, lane = tid & 31;
    #pragma unroll
    for (int it = 0; it < 4; it++) {
        int n = blockIdx.x * 32 + it * 8 + warp;
        if (n >= N_NODES) continue;
        float2 e2 = *(const float2*)(emb + (size_t)n * OUT_C + lane * 2);
        sEmb[warp][lane * 2] = e2.x;
        sEmb[warp][lane * 2 + 1] = e2.y;
        __syncwarp();
        #pragma unroll
        for (int w = 0; w < 4; w++) {
            int j = lane + w * 32;
            float acc = sb1[j];
            #pragma unroll 8
            for (int c = 0; c < OUT_C; c++) acc += sEmb[warp][c] * sW1[c * 128 + j];
            sHid[warp][j] = fmaxf(acc, 0.f);
        }
        __syncwarp();
        if (lane < K_CL) {
            float lg = sb2[lane];
            #pragma unroll 16
            for (int k = 0; k < 128; k++) lg += sHid[warp][k] * sW2[k * K_CL + lane];
            float mx = lg;
            #pragma unroll
            for (int m = 8; m >= 1; m >>= 1)
                mx = fmaxf(mx, __shfl_xor_sync(0xffff, mx, m, 16));
            float ev = __expf(lg - mx);
            float sum = ev;
            #pragma unroll
            for (int m = 8; m >= 1; m >>= 1)
                sum += __shfl_xor_sync(0xffff, sum, m, 16);
            s_out[(size_t)n * K_CL + lane] = ev / sum;
        }
        __syncwarp();
    }
}

// ---------------- launch ------------------------------------------------------
extern "C" void kernel_launch(void* const* d_in, const int* in_sizes, int n_in,
                              void* d_out, int out_size) {
    const float* x        = (const float*)d_in[0];
    const int*   ei       = (const int*)d_in[1];     // [2, E]: src then dst
    const float* W1       = (const float*)d_in[2];
    const float* att_src1 = (const float*)d_in[3];
    const float* att_dst1 = (const float*)d_in[4];
    const float* b1       = (const float*)d_in[5];
    const float* W2       = (const float*)d_in[6];
    const float* att_src2 = (const float*)d_in[7];
    const float* att_dst2 = (const float*)d_in[8];
    const float* b2       = (const float*)d_in[9];
    const float* Wm1      = (const float*)d_in[10];
    const float* bm1      = (const float*)d_in[11];
    const float* Wm2      = (const float*)d_in[12];
    const float* bm2      = (const float*)d_in[13];

    float* s_out = (float*)d_out;                           // [N, 16]
    float* emb   = (float*)d_out + (size_t)N_NODES * K_CL;  // [N, 64]

    float *ph1, *pout1, *ph2;
    cudaGetSymbolAddress((void**)&ph1, g_h1);
    cudaGetSymbolAddress((void**)&pout1, g_out1);
    cudaGetSymbolAddress((void**)&ph2, g_h2);
    unsigned *pw1hi, *pw1lo, *pw2hi, *pw2lo;
    cudaGetSymbolAddress((void**)&pw1hi, g_w1hi);
    cudaGetSymbolAddress((void**)&pw1lo, g_w1lo);
    cudaGetSymbolAddress((void**)&pw2hi, g_w2hi);
    cudaGetSymbolAddress((void**)&pw2lo, g_w2lo);

    // 1. prep: zero deg histogram + split W1/W2 to bf16 hi/lo
    prep_kernel<<<292, 256>>>(W1, W2);
    // 2. edge histogram (standalone, high occupancy)
    hist_kernel<<<(ETOT + 255) / 256, 256>>>(ei);
    // 3. CSR scan (single block) + scatter
    scan_all<<<1, 256>>>();
    scatter_kernel<<<(ETOT + 255) / 256, 256>>>(ei);

    // 4. h1 = x @ W1   [50000,128]x[128,256]  (bf16 3-product tensor cores)
    {
        dim3 grid(F1 / 128, (N_NODES + 127) / 128);
        gemm_bf16x3<128, false><<<grid, 256>>>(x, pw1hi, pw1lo, ph1, N_NODES, F1, IN_C);
    }
    // 5. attention dots layer 1
    att1_kernel<<<(N_NODES * HEADS + 255) / 256, 256>>>(att_src1, att_dst1);
    // 6. GAT layer 1 single-pass (b1 folded)
    gat1_csr<<<(N_NODES + 7) / 8, 256>>>(b1);
    // 7. h2 = ELU(out1) @ W2  [50000,256]x[256,64]  (ELU fused into A-split)
    {
        dim3 grid(OUT_C / 64, (N_NODES + 127) / 128);
        gemm_bf16x3<64, true><<<grid, 256>>>(pout1, pw2hi, pw2lo, ph2, N_NODES, OUT_C, F1);
    }
    // 8. attention dots layer 2
    att2_kernel<<<(N_NODES + 255) / 256, 256>>>(att_src2, att_dst2);
    // 9. GAT layer 2 single-pass -> embeddings (b2 folded)
    gat2_csr<<<(N_NODES + 7) / 8, 256>>>(emb, b2);
    // 10. MLP head + softmax -> s
    mlp_kernel<<<(N_NODES + 31) / 32, 256>>>(emb, Wm1, bm1, Wm2, bm2, s_out);
}

// round 11
// speedup vs baseline: 1.1933x; 1.1933x over previous
#include <cuda_runtime.h>
#include <math.h>

#define N_NODES 50000
#define NUM_E   400000
#define ETOT    (NUM_E + N_NODES)   // 450000, self-loops appended
#define IN_C    128
#define HID     32
#define HEADS   8
#define F1      (HEADS * HID)       // 256
#define OUT_C   64
#define K_CL    16
#define NEG_SLOPE 0.2f
#define EPS_F   1e-16f

// ---------------- scratch (device globals; no runtime allocation) -----------
__device__ float g_h1[(size_t)N_NODES * F1];     // x@W1
__device__ float g_out1[(size_t)N_NODES * F1];   // layer1 output (incl. b1)
__device__ float g_h2[(size_t)N_NODES * OUT_C];  // ELU(out1)@W2
__device__ float g_asrc1[N_NODES * HEADS];
__device__ float g_adst1[N_NODES * HEADS];
__device__ float g_asrc2[N_NODES];
__device__ float g_adst2[N_NODES];
// CSR by destination
__device__ int g_deg[N_NODES];
__device__ int g_start[N_NODES + 1];
__device__ int g_cursor[N_NODES];
__device__ int g_csr_src[ETOT];
__device__ int g_bsum[256];
// pre-split weights (packed bf16x2 along k-pairs): [K/2][N]
__device__ unsigned g_w1hi[(IN_C / 2) * F1];
__device__ unsigned g_w1lo[(IN_C / 2) * F1];
__device__ unsigned g_w2hi[(F1 / 2) * OUT_C];
__device__ unsigned g_w2lo[(F1 / 2) * OUT_C];

// ---------------- helpers ----------------------------------------------------
__device__ __forceinline__ float lrelu(float x) { return x > 0.f ? x : NEG_SLOPE * x; }
__device__ __forceinline__ float elu1(float x)  { return x > 0.f ? x : expm1f(x); }

__device__ __forceinline__ unsigned pack_bf16(float f_even, float f_odd) {
    unsigned r;
    asm("cvt.rn.satfinite.bf16x2.f32 %0, %1, %2;" : "=r"(r) : "f"(f_odd), "f"(f_even));
    return r;
}
__device__ __forceinline__ void bf16_split(float f0, float f1, unsigned& hi, unsigned& lo) {
    hi = pack_bf16(f0, f1);
    float b0 = __uint_as_float(hi << 16);
    float b1 = __uint_as_float(hi & 0xffff0000u);
    lo = pack_bf16(f0 - b0, f1 - b1);
}

#define MMA_BF16(d, a, b0_, b1_) \
    asm("mma.sync.aligned.m16n8k16.row.col.f32.bf16.bf16.f32 " \
        "{%0,%1,%2,%3}, {%4,%5,%6,%7}, {%8,%9}, {%0,%1,%2,%3};" \
        : "+f"(d[0]), "+f"(d[1]), "+f"(d[2]), "+f"(d[3]) \
        : "r"(a[0]), "r"(a[1]), "r"(a[2]), "r"(a[3]), "r"(b0_), "r"(b1_))

// ---------------- prep: zero degree hist + split both weight matrices --------
__global__ void prep_kernel(const float* __restrict__ W1, const float* __restrict__ W2) {
    int b = blockIdx.x, tid = threadIdx.x;
    if (b < 196) {
        int i = b * 256 + tid;
        if (i < N_NODES) g_deg[i] = 0;
    } else if (b < 196 + 64) {               // W1: (IN_C/2)*F1 = 16384 = 64*256
        int i = (b - 196) * 256 + tid;
        int kp = i >> 8, n = i & 255;
        unsigned h, l;
        bf16_split(W1[(size_t)(2 * kp) * F1 + n], W1[(size_t)(2 * kp + 1) * F1 + n], h, l);
        g_w1hi[i] = h; g_w1lo[i] = l;
    } else {                                  // W2: (F1/2)*OUT_C = 8192 = 32*256
        int i = (b - 260) * 256 + tid;
        int kp = i >> 6, n = i & 63;
        unsigned h, l;
        bf16_split(W2[(size_t)(2 * kp) * OUT_C + n], W2[(size_t)(2 * kp + 1) * OUT_C + n], h, l);
        g_w2hi[i] = h; g_w2lo[i] = l;
    }
}

// ---------------- edge histogram ---------------------------------------------
__global__ void hist_kernel(const int* __restrict__ ei) {
    int e = blockIdx.x * blockDim.x + threadIdx.x;
    if (e >= ETOT) return;
    int d = (e < NUM_E) ? ei[NUM_E + e] : e - NUM_E;
    atomicAdd(&g_deg[d], 1);
}

// ---------------- CSR: 3-kernel scan + scatter (round-6 proven) --------------
__global__ void scan1_kernel() {
    __shared__ int sm[256];
    int tid = threadIdx.x;
    int i = blockIdx.x * 256 + tid;
    int v = (i < N_NODES) ? g_deg[i] : 0;
    sm[tid] = v;
    __syncthreads();
    #pragma unroll
    for (int off = 1; off < 256; off <<= 1) {
        int t = (tid >= off) ? sm[tid - off] : 0;
        __syncthreads();
        sm[tid] += t;
        __syncthreads();
    }
    if (i < N_NODES) g_start[i] = sm[tid] - v;   // exclusive
    if (tid == 255) g_bsum[blockIdx.x] = sm[255];
}
__global__ void scan2_kernel(int nblocks) {
    __shared__ int sm[256];
    int tid = threadIdx.x;
    int v = (tid < nblocks) ? g_bsum[tid] : 0;
    sm[tid] = v;
    __syncthreads();
    #pragma unroll
    for (int off = 1; off < 256; off <<= 1) {
        int t = (tid >= off) ? sm[tid - off] : 0;
        __syncthreads();
        sm[tid] += t;
        __syncthreads();
    }
    if (tid < nblocks) g_bsum[tid] = sm[tid] - v;  // exclusive
}
__global__ void scan3_kernel() {
    int tid = threadIdx.x;
    int i = blockIdx.x * 256 + tid;
    if (i < N_NODES) {
        int s = g_start[i] + g_bsum[blockIdx.x];
        g_start[i] = s;
        g_cursor[i] = s;
    }
    if (i == 0) g_start[N_NODES] = ETOT;
}
__global__ void scatter_kernel(const int* __restrict__ ei) {
    int e = blockIdx.x * blockDim.x + threadIdx.x;
    if (e >= ETOT) return;
    int s, d;
    if (e < NUM_E) { s = ei[e]; d = ei[NUM_E + e]; } else { s = d = e - NUM_E; }
    int pos = atomicAdd(&g_cursor[d], 1);
    g_csr_src[pos] = s;
}

// ---------------- bf16 3-product tensor-core GEMM ----------------------------
#define AS_STRIDE 20
template<int BN, bool ELU_A>
__global__ __launch_bounds__(256, 2) void gemm_bf16x3(
    const float* __restrict__ A,
    const unsigned* __restrict__ Bhi, const unsigned* __restrict__ Blo,
    float* __restrict__ C, int M, int Nc, int Kc)
{
    constexpr int NATOM = BN / 16;
    constexpr int BS_STRIDE = BN + 8;
    __shared__ unsigned sAhi[128 * AS_STRIDE];
    __shared__ unsigned sAlo[128 * AS_STRIDE];
    __shared__ unsigned sBhi[16 * BS_STRIDE];
    __shared__ unsigned sBlo[16 * BS_STRIDE];

    const int tid = threadIdx.x;
    const int warp = tid >> 5, lane = tid & 31;
    const int g = lane >> 2, tig = lane & 3;
    const int rowA = blockIdx.y * 128, colB = blockIdx.x * BN;
    const int wm = (warp >> 1) * 32, wn = (warp & 1) * (BN / 2);

    float d[2][NATOM][4];
    #pragma unroll
    for (int i = 0; i < 2; i++)
        #pragma unroll
        for (int j = 0; j < NATOM; j++)
            #pragma unroll
            for (int q = 0; q < 4; q++) d[i][j][q] = 0.f;

    const int arow = tid >> 1;
    const int ak0  = (tid & 1) * 16;
    const bool arow_ok = (rowA + arow) < M;
    const float* Aptr = A + (size_t)(rowA + arow) * Kc + ak0;

    const int bkp = tid >> 4;
    const int bn0 = (tid & 15) * (BN / 16);

    const int KT = Kc / 32;
    for (int kt = 0; kt < KT; kt++) {
        {
            float4 f[4];
            #pragma unroll
            for (int q = 0; q < 4; q++)
                f[q] = arow_ok ? *(const float4*)(Aptr + kt * 32 + q * 4)
                               : make_float4(0.f, 0.f, 0.f, 0.f);
            if (ELU_A) {
                #pragma unroll
                for (int q = 0; q < 4; q++) {
                    f[q].x = elu1(f[q].x); f[q].y = elu1(f[q].y);
                    f[q].z = elu1(f[q].z); f[q].w = elu1(f[q].w);
                }
            }
            unsigned* hp = sAhi + arow * AS_STRIDE + (ak0 >> 1);
            unsigned* lp = sAlo + arow * AS_STRIDE + (ak0 >> 1);
            #pragma unroll
            for (int q = 0; q < 4; q++) {
                unsigned h0, l0, h1, l1;
                bf16_split(f[q].x, f[q].y, h0, l0);
                bf16_split(f[q].z, f[q].w, h1, l1);
                hp[q * 2] = h0; hp[q * 2 + 1] = h1;
                lp[q * 2] = l0; lp[q * 2 + 1] = l1;
            }
        }
        {
            const unsigned* gh = Bhi + (size_t)(kt * 16 + bkp) * Nc + colB + bn0;
            const unsigned* gl = Blo + (size_t)(kt * 16 + bkp) * Nc + colB + bn0;
            unsigned* sh = sBhi + bkp * BS_STRIDE + bn0;
            unsigned* sl = sBlo + bkp * BS_STRIDE + bn0;
            #pragma unroll
            for (int q = 0; q < BN / 64; q++) {
                ((int4*)sh)[q] = ((const int4*)gh)[q];
                ((int4*)sl)[q] = ((const int4*)gl)[q];
            }
        }
        __syncthreads();

        #pragma unroll
        for (int s = 0; s < 2; s++) {
            const int kp = s * 8 + tig;
            unsigned ahi[2][4], alo[2][4];
            #pragma unroll
            for (int am = 0; am < 2; am++) {
                int m0 = wm + am * 16 + g;
                ahi[am][0] = sAhi[m0 * AS_STRIDE + kp];
                ahi[am][1] = sAhi[(m0 + 8) * AS_STRIDE + kp];
                ahi[am][2] = sAhi[m0 * AS_STRIDE + kp + 4];
                ahi[am][3] = sAhi[(m0 + 8) * AS_STRIDE + kp + 4];
                alo[am][0] = sAlo[m0 * AS_STRIDE + kp];
                alo[am][1] = sAlo[(m0 + 8) * AS_STRIDE + kp];
                alo[am][2] = sAlo[m0 * AS_STRIDE + kp + 4];
                alo[am][3] = sAlo[(m0 + 8) * AS_STRIDE + kp + 4];
            }
            #pragma unroll
            for (int an = 0; an < NATOM; an++) {
                int n = wn + an * 8 + g;
                unsigned bh0 = sBhi[kp * BS_STRIDE + n];
                unsigned bh1 = sBhi[(kp + 4) * BS_STRIDE + n];
                unsigned bl0 = sBlo[kp * BS_STRIDE + n];
                unsigned bl1 = sBlo[(kp + 4) * BS_STRIDE + n];
                #pragma unroll
                for (int am = 0; am < 2; am++) {
                    MMA_BF16(d[am][an], ahi[am], bh0, bh1);
                    MMA_BF16(d[am][an], alo[am], bh0, bh1);
                    MMA_BF16(d[am][an], ahi[am], bl0, bl1);
                }
            }
        }
        __syncthreads();
    }

    #pragma unroll
    for (int am = 0; am < 2; am++) {
        int r0 = rowA + wm + am * 16 + g;
        #pragma unroll
        for (int an = 0; an < NATOM; an++) {
            int c = colB + wn + an * 8 + 2 * tig;
            if (r0 < M)
                *(float2*)&C[(size_t)r0 * Nc + c] = make_float2(d[am][an][0], d[am][an][1]);
            if (r0 + 8 < M)
                *(float2*)&C[(size_t)(r0 + 8) * Nc + c] = make_float2(d[am][an][2], d[am][an][3]);
        }
    }
}

// ---------------- attention dot products -------------------------------------
__global__ void att1_kernel(const float* __restrict__ att_src, const float* __restrict__ att_dst) {
    int idx = blockIdx.x * blockDim.x + threadIdx.x;
    if (idx >= N_NODES * HEADS) return;
    int n = idx >> 3, h = idx & 7;
    const float4* hp = (const float4*)(g_h1 + (size_t)n * F1 + h * HID);
    const float4* as = (const float4*)(att_src + h * HID);
    const float4* ad = (const float4*)(att_dst + h * HID);
    float s = 0.f, d = 0.f;
    #pragma unroll
    for (int i = 0; i < 8; i++) {
        float4 hv = hp[i], a = as[i], b = ad[i];
        s += hv.x * a.x + hv.y * a.y + hv.z * a.z + hv.w * a.w;
        d += hv.x * b.x + hv.y * b.y + hv.z * b.z + hv.w * b.w;
    }
    g_asrc1[idx] = s;
    g_adst1[idx] = d;
}

__global__ void att2_kernel(const float* __restrict__ att_src, const float* __restrict__ att_dst) {
    int n = blockIdx.x * blockDim.x + threadIdx.x;
    if (n >= N_NODES) return;
    const float4* hp = (const float4*)(g_h2 + (size_t)n * OUT_C);
    const float4* as = (const float4*)att_src;
    const float4* ad = (const float4*)att_dst;
    float s = 0.f, d = 0.f;
    #pragma unroll
    for (int i = 0; i < 16; i++) {
        float4 hv = hp[i], a = as[i], b = ad[i];
        s += hv.x * a.x + hv.y * a.y + hv.z * a.z + hv.w * a.w;
        d += hv.x * b.x + hv.y * b.y + hv.z * b.z + hv.w * b.w;
    }
    g_asrc2[n] = s;
    g_adst2[n] = d;
}

// ---------------- GAT layer 1: two-pass fused softmax + aggregation ----------
__global__ __launch_bounds__(256) void gat1_csr(const float* __restrict__ b1) {
    int warp = threadIdx.x >> 5, lane = threadIdx.x & 31;
    int n = blockIdx.x * 8 + warp;
    if (n >= N_NODES) return;
    int beg = g_start[n], end = g_start[n + 1];

    // pass 1: denominators for 8 heads; lane = (edge_group:2 | head:3)
    int h8 = lane & 7;
    int eg = lane >> 3;
    float adst_p1 = g_adst1[n * 8 + h8];
    float den = 0.f;
    for (int e0 = beg; e0 < end; e0 += 4) {
        int e = e0 + eg;
        if (e < end) {
            int s = g_csr_src[e];
            den += __expf(lrelu(g_asrc1[s * 8 + h8] + adst_p1));
        }
    }
    den += __shfl_xor_sync(0xffffffffu, den, 8);
    den += __shfl_xor_sync(0xffffffffu, den, 16);
    int head = lane >> 2;
    float inv = 1.f / (__shfl_sync(0xffffffffu, den, head) + EPS_F);
    float adst_h = g_adst1[n * 8 + head];

    // pass 2: accumulate alpha * h1[src] in registers (8 floats/lane)
    float4 a0 = ((const float4*)b1)[lane * 2];
    float4 a1 = ((const float4*)b1)[lane * 2 + 1];
    #pragma unroll 4
    for (int e = beg; e < end; e++) {
        int s = g_csr_src[e];
        float alpha = __expf(lrelu(g_asrc1[s * 8 + head] + adst_h)) * inv;
        const float4* hp = (const float4*)(g_h1 + (size_t)s * F1) + lane * 2;
        float4 v0 = hp[0], v1 = hp[1];
        a0.x += alpha * v0.x; a0.y += alpha * v0.y; a0.z += alpha * v0.z; a0.w += alpha * v0.w;
        a1.x += alpha * v1.x; a1.y += alpha * v1.y; a1.z += alpha * v1.z; a1.w += alpha * v1.w;
    }
    float4* op = (float4*)(g_out1 + (size_t)n * F1) + lane * 2;
    op[0] = a0; op[1] = a1;
}

// ---------------- GAT layer 2: two-pass, writes embeddings -------------------
__global__ __launch_bounds__(256) void gat2_csr(float* __restrict__ emb, const float* __restrict__ b2) {
    int warp = threadIdx.x >> 5, lane = threadIdx.x & 31;
    int n = blockIdx.x * 8 + warp;
    if (n >= N_NODES) return;
    int beg = g_start[n], end = g_start[n + 1];
    float adst = g_adst2[n];

    float den = 0.f;
    for (int e = beg + lane; e < end; e += 32)
        den += __expf(lrelu(g_asrc2[g_csr_src[e]] + adst));
    #pragma unroll
    for (int m = 16; m >= 1; m >>= 1) den += __shfl_xor_sync(0xffffffffu, den, m);
    float inv = 1.f / (den + EPS_F);

    float2 acc = *(const float2*)(b2 + lane * 2);
    #pragma unroll 4
    for (int e = beg; e < end; e++) {
        int s = g_csr_src[e];
        float alpha = __expf(lrelu(g_asrc2[s] + adst)) * inv;
        float2 v = *(const float2*)(g_h2 + (size_t)s * OUT_C + lane * 2);
        acc.x += alpha * v.x;
        acc.y += alpha * v.y;
    }
    *(float2*)(emb + (size_t)n * OUT_C + lane * 2) = acc;
}

// ---------------- fused MLP head + softmax (64 nodes/block) ------------------
__global__ __launch_bounds__(256) void mlp_kernel(
    const float* __restrict__ emb,
    const float* __restrict__ Wm1, const float* __restrict__ bm1,
    const float* __restrict__ Wm2, const float* __restrict__ bm2,
    float* __restrict__ s_out)
{
    __shared__ float sW1[OUT_C * 128];   // 32 KB
    __shared__ float sW2[128 * K_CL];    // 8 KB
    __shared__ float sb1[128];
    __shared__ float sb2[K_CL];
    __shared__ float sHid[8][128];
    __shared__ float sEmb[8][OUT_C];
    int tid = threadIdx.x;
    for (int i = tid; i < OUT_C * 128; i += 256) sW1[i] = Wm1[i];
    for (int i = tid; i < 128 * K_CL; i += 256) sW2[i] = Wm2[i];
    if (tid < 128) sb1[tid] = bm1[tid];
    if (tid < K_CL) sb2[tid] = bm2[tid];
    __syncthreads();
    int warp = tid >> 5, lane = tid & 31;
    #pragma unroll
    for (int it = 0; it < 8; it++) {
        int n = blockIdx.x * 64 + it * 8 + warp;
        if (n >= N_NODES) continue;
        float2 e2 = *(const float2*)(emb + (size_t)n * OUT_C + lane * 2);
        sEmb[warp][lane * 2] = e2.x;
        sEmb[warp][lane * 2 + 1] = e2.y;
        __syncwarp();
        #pragma unroll
        for (int w = 0; w < 4; w++) {
            int j = lane + w * 32;
            float acc = sb1[j];
            #pragma unroll 8
            for (int c = 0; c < OUT_C; c++) acc += sEmb[warp][c] * sW1[c * 128 + j];
            sHid[warp][j] = fmaxf(acc, 0.f);
        }
        __syncwarp();
        if (lane < K_CL) {
            float lg = sb2[lane];
            #pragma unroll 16
            for (int k = 0; k < 128; k++) lg += sHid[warp][k] * sW2[k * K_CL + lane];
            float mx = lg;
            #pragma unroll
            for (int m = 8; m >= 1; m >>= 1)
                mx = fmaxf(mx, __shfl_xor_sync(0xffff, mx, m, 16));
            float ev = __expf(lg - mx);
            float sum = ev;
            #pragma unroll
            for (int m = 8; m >= 1; m >>= 1)
                sum += __shfl_xor_sync(0xffff, sum, m, 16);
            s_out[(size_t)n * K_CL + lane] = ev / sum;
        }
        __syncwarp();
    }
}

// ---------------- launch ------------------------------------------------------
extern "C" void kernel_launch(void* const* d_in, const int* in_sizes, int n_in,
                              void* d_out, int out_size) {
    const float* x        = (const float*)d_in[0];
    const int*   ei       = (const int*)d_in[1];     // [2, E]: src then dst
    const float* W1       = (const float*)d_in[2];
    const float* att_src1 = (const float*)d_in[3];
    const float* att_dst1 = (const float*)d_in[4];
    const float* b1       = (const float*)d_in[5];
    const float* W2       = (const float*)d_in[6];
    const float* att_src2 = (const float*)d_in[7];
    const float* att_dst2 = (const float*)d_in[8];
    const float* b2       = (const float*)d_in[9];
    const float* Wm1      = (const float*)d_in[10];
    const float* bm1      = (const float*)d_in[11];
    const float* Wm2      = (const float*)d_in[12];
    const float* bm2      = (const float*)d_in[13];

    float* s_out = (float*)d_out;                           // [N, 16]
    float* emb   = (float*)d_out + (size_t)N_NODES * K_CL;  // [N, 64]

    float *ph1, *pout1, *ph2;
    cudaGetSymbolAddress((void**)&ph1, g_h1);
    cudaGetSymbolAddress((void**)&pout1, g_out1);
    cudaGetSymbolAddress((void**)&ph2, g_h2);
    unsigned *pw1hi, *pw1lo, *pw2hi, *pw2lo;
    cudaGetSymbolAddress((void**)&pw1hi, g_w1hi);
    cudaGetSymbolAddress((void**)&pw1lo, g_w1lo);
    cudaGetSymbolAddress((void**)&pw2hi, g_w2hi);
    cudaGetSymbolAddress((void**)&pw2lo, g_w2lo);

    const int NSCAN = (N_NODES + 255) / 256;   // 196

    // 1. prep: zero deg histogram + split W1/W2 to bf16 hi/lo (one kernel)
    prep_kernel<<<292, 256>>>(W1, W2);
    // 2. CSR build (round-6 proven structure)
    hist_kernel<<<(ETOT + 255) / 256, 256>>>(ei);
    scan1_kernel<<<NSCAN, 256>>>();
    scan2_kernel<<<1, 256>>>(NSCAN);
    scan3_kernel<<<NSCAN, 256>>>();
    scatter_kernel<<<(ETOT + 255) / 256, 256>>>(ei);

    // 3. h1 = x @ W1   [50000,128]x[128,256]  (bf16 3-product tensor cores)
    {
        dim3 grid(F1 / 128, (N_NODES + 127) / 128);
        gemm_bf16x3<128, false><<<grid, 256>>>(x, pw1hi, pw1lo, ph1, N_NODES, F1, IN_C);
    }
    // 4. attention dots layer 1
    att1_kernel<<<(N_NODES * HEADS + 255) / 256, 256>>>(att_src1, att_dst1);
    // 5. GAT layer 1 (b1 folded)
    gat1_csr<<<(N_NODES + 7) / 8, 256>>>(b1);
    // 6. h2 = ELU(out1) @ W2  [50000,256]x[256,64]  (ELU fused into A-split)
    {
        dim3 grid(OUT_C / 64, (N_NODES + 127) / 128);
        gemm_bf16x3<64, true><<<grid, 256>>>(pout1, pw2hi, pw2lo, ph2, N_NODES, OUT_C, F1);
    }
    // 7. attention dots layer 2
    att2_kernel<<<(N_NODES + 255) / 256, 256>>>(att_src2, att_dst2);
    // 8. GAT layer 2 -> embeddings (b2 folded)
    gat2_csr<<<(N_NODES + 7) / 8, 256>>>(emb, b2);
    // 9. MLP head + softmax -> s
    mlp_kernel<<<(N_NODES + 63) / 64, 256>>>(emb, Wm1, bm1, Wm2, bm2, s_out);
}